// round 1
// baseline (speedup 1.0000x reference)
// LinearNO on GB300 — algebraically collapsed linear attention.
// Pipeline:
//  K0: A_qk[512][64] = W_in @ blockdiag(W_q | W_k) per head ; c_qk biases
//  K1: q_logits,k_logits[b][32][n] = x @ A_qk + c   (f32x2 tiled GEMM)
//  K2: per-(b,hr) max & 1/sum-exp over N (k softmax stats)
//  K3: S[b][hr][512] = sum_n softmax_k(n) * x[b,n,:]  (partials, deterministic)
//  K5: U[b][hr][512] = ((S @ W_in_h + b_in_h) @ W_v) @ W_out_h
//  K6: out[b,n,:] = b_out + sum_hr softmax_q(hr) * U[b][hr][:]
#include <cuda_runtime.h>
#include <cstdint>

typedef unsigned long long ull;

#define Bb   8
#define Nn   16384
#define DIMM 512
#define Hh   8
#define DHh  64
#define Rr   4
#define Jj   32          // Hh*Rr
#define SCH  32          // S-reduction chunks per batch

// ---------------- scratch (device globals; no allocation) ----------------
__device__ float g_Aqk[DIMM * 64];
__device__ float g_cqk[64];
__device__ float g_qlog[(size_t)Bb * Jj * Nn];   // [b][j][n]
__device__ float g_klog[(size_t)Bb * Jj * Nn];   // [b][j][n]
__device__ float g_M[Bb * Jj];
__device__ float g_Zi[Bb * Jj];
__device__ float g_Spart[(size_t)Bb * SCH * Jj * DIMM];
__device__ float g_U[(size_t)Bb * Jj * DIMM];

// ---------------- helpers ----------------
__device__ __forceinline__ ull ffma2(ull a, ull b, ull c) {
    ull d;
    asm("fma.rn.f32x2 %0, %1, %2, %3;" : "=l"(d) : "l"(a), "l"(b), "l"(c));
    return d;
}
__device__ __forceinline__ ull dup_f(float f) {
    unsigned u = __float_as_uint(f);
    return (ull)u | ((ull)u << 32);
}
__device__ __forceinline__ float ulo(ull u) { return __uint_as_float((unsigned)u); }
__device__ __forceinline__ float uhi(ull u) { return __uint_as_float((unsigned)(u >> 32)); }

// ---------------- K0: fold head projections into input weights ----------------
__global__ void k0_prep(const float* __restrict__ W_in, const float* __restrict__ b_in,
                        const float* __restrict__ W_q, const float* __restrict__ W_k) {
    int j = blockIdx.x;                      // 0..63 (q: 0..31, k: 32..63)
    const float* Wqk = (j < 32) ? W_q : W_k;
    int jj = j & 31, h = jj >> 2, r = jj & 3;
    int D = threadIdx.x;                     // 512 threads
    const float* wrow = W_in + (size_t)D * DIMM + h * DHh;
    float s = 0.f;
    #pragma unroll 8
    for (int d = 0; d < DHh; d++) s += wrow[d] * Wqk[d * Rr + r];
    g_Aqk[(size_t)D * 64 + j] = s;
    if (D == 0) {
        float c = 0.f;
        for (int d = 0; d < DHh; d++) c += b_in[h * DHh + d] * Wqk[d * Rr + r];
        g_cqk[j] = c;
    }
}

// ---------------- K1: logits = x @ A_qk + c  (64 rows x 64 cols per block) ----------
__global__ void __launch_bounds__(256) k1_logits(const float* __restrict__ x) {
    extern __shared__ char sm1[];
    float* ws  = (float*)sm1;                         // 512*64 f32 = 128KB (full weights)
    ull*   xs2 = (ull*)(sm1 + DIMM * 64 * 4);         // 64k x 64row duplicated = 32KB
    float* stag = (float*)xs2;                        // reused for output transpose

    int tid = threadIdx.x;
    // load weights into smem
    {
        const float4* src = (const float4*)g_Aqk;
        float4* dst = (float4*)ws;
        for (int i = tid; i < DIMM * 64 / 4; i += 256) dst[i] = src[i];
    }
    size_t row0 = (size_t)blockIdx.x * 64;
    const float* xb = x + row0 * DIMM;
    int tx = tid & 15, ty = tid >> 4;
    int c0 = tx * 4, r0g = ty * 4;

    ull acc[4][2];
    #pragma unroll
    for (int i = 0; i < 4; i++) { acc[i][0] = 0ull; acc[i][1] = 0ull; }

    for (int kc = 0; kc < 8; kc++) {
        __syncthreads();   // weights ready (kc=0) + previous xs2 readers done
        #pragma unroll
        for (int i = 0; i < 4; i++) {
            int idx = tid + i * 256;          // 0..1023 float4 tiles
            int row = idx >> 4, kq = idx & 15;
            float4 v = *(const float4*)(xb + (size_t)row * DIMM + kc * 64 + kq * 4);
            int kb = kq * 4;
            xs2[(kb + 0) * 64 + row] = dup_f(v.x);
            xs2[(kb + 1) * 64 + row] = dup_f(v.y);
            xs2[(kb + 2) * 64 + row] = dup_f(v.z);
            xs2[(kb + 3) * 64 + row] = dup_f(v.w);
        }
        __syncthreads();
        const float* wsk = ws + kc * 64 * 64;
        #pragma unroll 8
        for (int k = 0; k < 64; k++) {
            ulonglong2 A0 = *(const ulonglong2*)(xs2 + k * 64 + r0g);
            ulonglong2 A1 = *(const ulonglong2*)(xs2 + k * 64 + r0g + 2);
            ulonglong2 Bv = *(const ulonglong2*)(wsk + k * 64 + c0);
            acc[0][0] = ffma2(A0.x, Bv.x, acc[0][0]);
            acc[0][1] = ffma2(A0.x, Bv.y, acc[0][1]);
            acc[1][0] = ffma2(A0.y, Bv.x, acc[1][0]);
            acc[1][1] = ffma2(A0.y, Bv.y, acc[1][1]);
            acc[2][0] = ffma2(A1.x, Bv.x, acc[2][0]);
            acc[2][1] = ffma2(A1.x, Bv.y, acc[2][1]);
            acc[3][0] = ffma2(A1.y, Bv.x, acc[3][0]);
            acc[3][1] = ffma2(A1.y, Bv.y, acc[3][1]);
        }
    }
    __syncthreads();  // all compute reads of xs2 done before staging reuse
    #pragma unroll
    for (int i = 0; i < 4; i++) {
        int r = r0g + i;
        stag[(c0 + 0) * 65 + r] = ulo(acc[i][0]) + g_cqk[c0 + 0];
        stag[(c0 + 1) * 65 + r] = uhi(acc[i][0]) + g_cqk[c0 + 1];
        stag[(c0 + 2) * 65 + r] = ulo(acc[i][1]) + g_cqk[c0 + 2];
        stag[(c0 + 3) * 65 + r] = uhi(acc[i][1]) + g_cqk[c0 + 3];
    }
    __syncthreads();
    int b = (int)(row0 >> 14);
    int nb = (int)(row0 & (Nn - 1));
    #pragma unroll
    for (int i = 0; i < 16; i++) {
        int idx = tid + i * 256;           // 4096 values
        int c = idx >> 6, rr = idx & 63;
        float v = stag[c * 65 + rr];
        if (c < 32) g_qlog[((size_t)(b * Jj + c)) * Nn + nb + rr] = v;
        else        g_klog[((size_t)(b * Jj + (c - 32))) * Nn + nb + rr] = v;
    }
}

// ---------------- K2: k-softmax stats over N ----------------
__global__ void k2_stats() {
    int bj = blockIdx.x;
    const float* kl = g_klog + (size_t)bj * Nn;
    __shared__ float red[256];
    int tid = threadIdx.x;
    float m = -3.4e38f;
    for (int i = tid; i < Nn; i += 256) m = fmaxf(m, kl[i]);
    red[tid] = m; __syncthreads();
    for (int s = 128; s > 0; s >>= 1) {
        if (tid < s) red[tid] = fmaxf(red[tid], red[tid + s]);
        __syncthreads();
    }
    float M = red[0];
    __syncthreads();
    float sum = 0.f;
    for (int i = tid; i < Nn; i += 256) sum += __expf(kl[i] - M);
    red[tid] = sum; __syncthreads();
    for (int s = 128; s > 0; s >>= 1) {
        if (tid < s) red[tid] += red[tid + s];
        __syncthreads();
    }
    if (tid == 0) { g_M[bj] = M; g_Zi[bj] = 1.0f / red[0]; }
}

// ---------------- K3: S partials = sum_n w[n,j] * x[n,:] ----------------
__global__ void __launch_bounds__(256) k3_S(const float* __restrict__ x) {
    extern __shared__ char sm3[];
    float* klc  = (float*)sm3;                        // [32][512] = 64KB
    float* xs   = klc + Jj * 512;                     // [8][512]  = 16KB
    ull*   wdup = (ull*)(xs + 8 * 512);               // [8][32]   = 2KB
    float* Msh  = (float*)(wdup + 8 * 32);
    float* Zsh  = Msh + 32;

    int tid = threadIdx.x;
    int blk = blockIdx.x;
    int b = blk >> 5, ch = blk & 31;
    int n0 = ch * 512;

    #pragma unroll
    for (int i = 0; i < 16; i++) {
        int idx = tid + i * 256;                 // 4096 float4
        int j = idx >> 7, nq = idx & 127;
        ((float4*)klc)[j * 128 + nq] =
            *(const float4*)(g_klog + ((size_t)(b * Jj + j)) * Nn + n0 + nq * 4);
    }
    if (tid < 32) { Msh[tid] = g_M[b * Jj + tid]; Zsh[tid] = g_Zi[b * Jj + tid]; }

    int jg = tid >> 5, j0 = jg * 4;              // 8 groups of 4 j
    int dg = tid & 31, d0 = dg * 16;             // 32 groups of 16 d
    ull acc[4][8];
    #pragma unroll
    for (int a = 0; a < 4; a++)
        #pragma unroll
        for (int c = 0; c < 8; c++) acc[a][c] = 0ull;

    const float* xb = x + ((size_t)(b * Nn + n0)) * DIMM;

    for (int ns = 0; ns < 512; ns += 8) {
        __syncthreads();   // klc ready (first iter) + xs/wdup readers done
        #pragma unroll
        for (int i = 0; i < 4; i++) {
            int idx = tid + i * 256;             // 1024 float4
            int row = idx >> 7, kq = idx & 127;
            ((float4*)xs)[row * 128 + kq] =
                *(const float4*)(xb + (size_t)(ns + row) * DIMM + kq * 4);
        }
        {
            int jw = tid & 31, nn = tid >> 5;
            float w = __expf(klc[jw * 512 + ns + nn] - Msh[jw]) * Zsh[jw];
            wdup[nn * 32 + jw] = dup_f(w);
        }
        __syncthreads();
        #pragma unroll
        for (int nn = 0; nn < 8; nn++) {
            ulonglong2 w01 = *(const ulonglong2*)(wdup + nn * 32 + j0);
            ulonglong2 w23 = *(const ulonglong2*)(wdup + nn * 32 + j0 + 2);
            ull wv[4] = { w01.x, w01.y, w23.x, w23.y };
            const ulonglong2* xp = (const ulonglong2*)(xs + nn * 512 + d0);
            ulonglong2 x0 = xp[0], x1 = xp[1], x2 = xp[2], x3 = xp[3];
            ull xv[8] = { x0.x, x0.y, x1.x, x1.y, x2.x, x2.y, x3.x, x3.y };
            #pragma unroll
            for (int a = 0; a < 4; a++)
                #pragma unroll
                for (int c = 0; c < 8; c++)
                    acc[a][c] = ffma2(wv[a], xv[c], acc[a][c]);
        }
    }
    float* dst = g_Spart + ((size_t)(b * SCH + ch)) * Jj * DIMM;
    #pragma unroll
    for (int a = 0; a < 4; a++) {
        int j = j0 + a;
        #pragma unroll
        for (int c = 0; c < 8; c++) {
            dst[(size_t)j * DIMM + d0 + 2 * c]     = ulo(acc[a][c]);
            dst[(size_t)j * DIMM + d0 + 2 * c + 1] = uhi(acc[a][c]);
        }
    }
}

// ---------------- K5: reduce S partials, compute U ----------------
__global__ void k5_U(const float* __restrict__ W_in, const float* __restrict__ b_in,
                     const float* __restrict__ W_v, const float* __restrict__ W_out) {
    int bj = blockIdx.x;
    int b = bj >> 5, j = bj & 31, h = j >> 2;
    __shared__ float Srow[DIMM];
    __shared__ float T[DHh];
    __shared__ float kv[DHh];
    int tid = threadIdx.x;   // 512
    {
        float s = 0.f;
        for (int ch = 0; ch < SCH; ch++)
            s += g_Spart[(((size_t)(b * SCH + ch)) * Jj + j) * DIMM + tid];
        Srow[tid] = s;
    }
    __syncthreads();
    if (tid < DHh) {
        float t = b_in[h * DHh + tid];
        for (int D = 0; D < DIMM; D++) t += Srow[D] * W_in[(size_t)D * DIMM + h * DHh + tid];
        T[tid] = t;
    }
    __syncthreads();
    if (tid < DHh) {
        float s = 0.f;
        for (int d = 0; d < DHh; d++) s += T[d] * W_v[d * DHh + tid];
        kv[tid] = s;
    }
    __syncthreads();
    {
        float u = 0.f;
        for (int c = 0; c < DHh; c++) u += kv[c] * W_out[(size_t)(h * DHh + c) * DIMM + tid];
        g_U[(size_t)bj * DIMM + tid] = u;
    }
}

// ---------------- K6: out = b_out + softmax_q @ U ----------------
__global__ void __launch_bounds__(256) k6_out(const float* __restrict__ b_out,
                                              float* __restrict__ out) {
    __shared__ float ql[Jj * 64];       // raw q logits [j][n]
    __shared__ ull   qd[64 * Jj];       // duplicated softmax weights [n][j]
    __shared__ float us[Jj * 128];      // U sub-tile [j][e]
    __shared__ float bo[128];
    int tid = threadIdx.x;
    int b = blockIdx.z;
    int n0 = blockIdx.y * 64;
    int e0 = blockIdx.x * 128;

    #pragma unroll
    for (int i = 0; i < 2; i++) {
        int idx = tid + i * 256;        // 512 float4
        int j = idx >> 4, nq = idx & 15;
        ((float4*)ql)[j * 16 + nq] =
            *(const float4*)(g_qlog + ((size_t)(b * Jj + j)) * Nn + n0 + nq * 4);
    }
    #pragma unroll
    for (int i = 0; i < 4; i++) {
        int idx = tid + i * 256;        // 1024 float4
        int j = idx >> 5, eq = idx & 31;
        ((float4*)us)[j * 32 + eq] =
            *(const float4*)(g_U + ((size_t)(b * Jj + j)) * DIMM + e0 + eq * 4);
    }
    if (tid < 32) ((float4*)bo)[tid] = *(const float4*)(b_out + e0 + tid * 4);
    __syncthreads();
    #pragma unroll
    for (int i = 0; i < 2; i++) {
        int p = tid + i * 256;          // 512 (n,h) pairs
        int n = p >> 3, h = p & 7;
        float v0 = ql[(h * 4 + 0) * 64 + n];
        float v1 = ql[(h * 4 + 1) * 64 + n];
        float v2 = ql[(h * 4 + 2) * 64 + n];
        float v3 = ql[(h * 4 + 3) * 64 + n];
        float mx = fmaxf(fmaxf(v0, v1), fmaxf(v2, v3));
        float e0f = __expf(v0 - mx), e1f = __expf(v1 - mx);
        float e2f = __expf(v2 - mx), e3f = __expf(v3 - mx);
        float inv = 1.0f / (e0f + e1f + e2f + e3f);
        qd[n * Jj + h * 4 + 0] = dup_f(e0f * inv);
        qd[n * Jj + h * 4 + 1] = dup_f(e1f * inv);
        qd[n * Jj + h * 4 + 2] = dup_f(e2f * inv);
        qd[n * Jj + h * 4 + 3] = dup_f(e3f * inv);
    }
    __syncthreads();

    int tx = tid & 15, ty = tid >> 4;
    int el = tx * 8, nl = ty * 4;
    ull acc[4][4];
    #pragma unroll
    for (int i = 0; i < 4; i++)
        #pragma unroll
        for (int p = 0; p < 4; p++) acc[i][p] = 0ull;

    #pragma unroll 4
    for (int j = 0; j < Jj; j++) {
        ull a0 = qd[(nl + 0) * Jj + j];
        ull a1 = qd[(nl + 1) * Jj + j];
        ull a2 = qd[(nl + 2) * Jj + j];
        ull a3 = qd[(nl + 3) * Jj + j];
        ulonglong2 b01 = *(const ulonglong2*)(us + j * 128 + el);
        ulonglong2 b23 = *(const ulonglong2*)(us + j * 128 + el + 4);
        acc[0][0] = ffma2(a0, b01.x, acc[0][0]); acc[0][1] = ffma2(a0, b01.y, acc[0][1]);
        acc[0][2] = ffma2(a0, b23.x, acc[0][2]); acc[0][3] = ffma2(a0, b23.y, acc[0][3]);
        acc[1][0] = ffma2(a1, b01.x, acc[1][0]); acc[1][1] = ffma2(a1, b01.y, acc[1][1]);
        acc[1][2] = ffma2(a1, b23.x, acc[1][2]); acc[1][3] = ffma2(a1, b23.y, acc[1][3]);
        acc[2][0] = ffma2(a2, b01.x, acc[2][0]); acc[2][1] = ffma2(a2, b01.y, acc[2][1]);
        acc[2][2] = ffma2(a2, b23.x, acc[2][2]); acc[2][3] = ffma2(a2, b23.y, acc[2][3]);
        acc[3][0] = ffma2(a3, b01.x, acc[3][0]); acc[3][1] = ffma2(a3, b01.y, acc[3][1]);
        acc[3][2] = ffma2(a3, b23.x, acc[3][2]); acc[3][3] = ffma2(a3, b23.y, acc[3][3]);
    }

    float* ob = out + ((size_t)b * Nn + n0 + nl) * DIMM + e0 + el;
    #pragma unroll
    for (int i = 0; i < 4; i++) {
        float4 v0, v1;
        v0.x = ulo(acc[i][0]) + bo[el + 0];
        v0.y = uhi(acc[i][0]) + bo[el + 1];
        v0.z = ulo(acc[i][1]) + bo[el + 2];
        v0.w = uhi(acc[i][1]) + bo[el + 3];
        v1.x = ulo(acc[i][2]) + bo[el + 4];
        v1.y = uhi(acc[i][2]) + bo[el + 5];
        v1.z = ulo(acc[i][3]) + bo[el + 6];
        v1.w = uhi(acc[i][3]) + bo[el + 7];
        *(float4*)(ob + (size_t)i * DIMM)     = v0;
        *(float4*)(ob + (size_t)i * DIMM + 4) = v1;
    }
}

// ---------------- launch ----------------
extern "C" void kernel_launch(void* const* d_in, const int* in_sizes, int n_in,
                              void* d_out, int out_size) {
    const float* x     = (const float*)d_in[0];
    const float* W_in  = (const float*)d_in[1];
    const float* b_in  = (const float*)d_in[2];
    const float* W_q   = (const float*)d_in[3];
    const float* W_k   = (const float*)d_in[4];
    const float* W_v   = (const float*)d_in[5];
    const float* W_out = (const float*)d_in[6];
    const float* b_out = (const float*)d_in[7];
    float* out = (float*)d_out;

    static int attrs_set = 0;
    // idempotent attribute configuration (not a work guard; launches below run every call)
    cudaFuncSetAttribute(k1_logits, cudaFuncAttributeMaxDynamicSharedMemorySize, 163840);
    cudaFuncSetAttribute(k3_S,      cudaFuncAttributeMaxDynamicSharedMemorySize, 84224);
    (void)attrs_set;

    k0_prep<<<64, 512>>>(W_in, b_in, W_q, W_k);
    k1_logits<<<(Bb * Nn) / 64, 256, 163840>>>(x);
    k2_stats<<<Bb * Jj, 256>>>();
    k3_S<<<Bb * SCH, 256, 84224>>>(x);
    k5_U<<<Bb * Jj, 512>>>(W_in, b_in, W_v, W_out);
    dim3 g6(DIMM / 128, Nn / 64, Bb);
    k6_out<<<g6, 256>>>(b_out, out);
}

// round 2
// speedup vs baseline: 1.9875x; 1.9875x over previous
// LinearNO on GB300 — collapsed linear attention, round 2:
// occupancy + cp.async double-buffering + broadcast-LDS/reg-dup f32x2 GEMM cores.
//  K0: A_qk[512][64] = W_in @ blockdiag(W_q|W_k); c_qk biases
//  K1: q/k logits = x @ A_qk + c  (256x64 tile, streamed weights, writes klogT too)
//  K2: per-(b,j) max & 1/sum-exp over N
//  K3: Spart[b][ch][32][512] = sum_n softmax_k(n) * x[n,:]  (fma-bound tiling)
//  K5: U[b][j][512] = ((S @ W_in_h + b_in_h) @ W_v) @ W_out_h
//  K6: out = b_out + softmax_q @ U
#include <cuda_runtime.h>
#include <cstdint>

typedef unsigned long long ull;

#define Bb   8
#define Nn   16384
#define DIMM 512
#define Hh   8
#define DHh  64
#define Rr   4
#define Jj   32
#define SCH  64          // K3 chunks per batch (256 n each)

// ---------------- scratch ----------------
__device__ __align__(16) float g_Aqk[DIMM * 64];
__device__ __align__(16) float g_cqk[64];
__device__ __align__(16) float g_qlog[(size_t)Bb * Jj * Nn];   // [b][j][n]
__device__ __align__(16) float g_klog[(size_t)Bb * Jj * Nn];   // [b][j][n]
__device__ __align__(16) float g_klogT[(size_t)Bb * Nn * Jj];  // [b][n][j]
__device__ __align__(16) float g_M[Bb * Jj];
__device__ __align__(16) float g_Zi[Bb * Jj];
__device__ __align__(16) float g_Spart[(size_t)Bb * SCH * Jj * DIMM];
__device__ __align__(16) float g_U[(size_t)Bb * Jj * DIMM];

// ---------------- helpers ----------------
__device__ __forceinline__ ull ffma2(ull a, ull b, ull c) {
    ull d;
    asm("fma.rn.f32x2 %0, %1, %2, %3;" : "=l"(d) : "l"(a), "l"(b), "l"(c));
    return d;
}
__device__ __forceinline__ ull dup2(float f) {
    unsigned u = __float_as_uint(f);
    ull d;
    asm("mov.b64 %0, {%1, %1};" : "=l"(d) : "r"(u));
    return d;
}
__device__ __forceinline__ float ulo(ull u) { return __uint_as_float((unsigned)u); }
__device__ __forceinline__ float uhi(ull u) { return __uint_as_float((unsigned)(u >> 32)); }

__device__ __forceinline__ void cpa16(uint32_t smem_dst, const void* gsrc) {
    asm volatile("cp.async.cg.shared.global [%0], [%1], 16;" :: "r"(smem_dst), "l"(gsrc));
}
__device__ __forceinline__ void cpa_commit() { asm volatile("cp.async.commit_group;"); }
__device__ __forceinline__ void cpa_wait1() { asm volatile("cp.async.wait_group 1;"); }
__device__ __forceinline__ void cpa_wait0() { asm volatile("cp.async.wait_group 0;"); }

// ---------------- K0 ----------------
__global__ void k0_prep(const float* __restrict__ W_in, const float* __restrict__ b_in,
                        const float* __restrict__ W_q, const float* __restrict__ W_k) {
    int j = blockIdx.x;                      // 0..63 (q: 0..31, k: 32..63)
    const float* Wqk = (j < 32) ? W_q : W_k;
    int jj = j & 31, h = jj >> 2, r = jj & 3;
    int D = threadIdx.x;                     // 512 threads
    const float* wrow = W_in + (size_t)D * DIMM + h * DHh;
    float s = 0.f;
    #pragma unroll 8
    for (int d = 0; d < DHh; d++) s += wrow[d] * Wqk[d * Rr + r];
    g_Aqk[(size_t)D * 64 + j] = s;
    if (D == 0) {
        float c = 0.f;
        for (int d = 0; d < DHh; d++) c += b_in[h * DHh + d] * Wqk[d * Rr + r];
        g_cqk[j] = c;
    }
}

// ---------------- K1: logits. 256 rows x 64 cols per CTA, 256 threads ----------------
// smem: xs[2][256][36] f32 (73728B) | ws[2][32][64] f32 (16384B); stag reuses xs.
#define K1_XBUF   9216      // floats per x buffer (256*36)
#define K1_WBUF   2048      // floats per w buffer (32*64)
#define K1_SMEM   90112

__global__ void __launch_bounds__(256, 2) k1_logits(const float* __restrict__ x) {
    extern __shared__ char sm[];
    float* xs = (float*)sm;
    float* ws = (float*)(sm + 73728);
    int tid = threadIdx.x;
    int cg = tid & 7, rg = tid >> 3;
    int c0 = cg * 8;
    size_t row0 = (size_t)blockIdx.x * 256;
    const float* xb = x + row0 * DIMM;
    uint32_t xs_s = (uint32_t)__cvta_generic_to_shared(xs);
    uint32_t ws_s = (uint32_t)__cvta_generic_to_shared(ws);

    ull acc[8][4];
    #pragma unroll
    for (int i = 0; i < 8; i++)
        #pragma unroll
        for (int m = 0; m < 4; m++) acc[i][m] = 0ull;

    // stage issue: x rows natural [row][36pad], w chunk natural [k][64]
    #define K1_ISSUE(s) do {                                                     \
        int buf_ = (s) & 1;                                                      \
        const float* src_ = xb + (size_t)tid * DIMM + (s) * 32;                  \
        uint32_t dst_ = xs_s + (uint32_t)(buf_ * 36864 + tid * 144);             \
        _Pragma("unroll")                                                        \
        for (int i_ = 0; i_ < 8; i_++) cpa16(dst_ + i_ * 16, src_ + i_ * 4);     \
        const float* wsrc_ = g_Aqk + (s) * 32 * 64;                              \
        uint32_t wdst_ = ws_s + (uint32_t)(buf_ * 8192);                         \
        _Pragma("unroll")                                                        \
        for (int i_ = 0; i_ < 2; i_++) {                                         \
            int c_ = tid * 2 + i_;                                               \
            cpa16(wdst_ + c_ * 16, wsrc_ + c_ * 4);                              \
        }                                                                        \
    } while (0)

    K1_ISSUE(0); cpa_commit();
    for (int s = 0; s < 16; s++) {
        if (s < 15) { K1_ISSUE(s + 1); cpa_commit(); cpa_wait1(); }
        else        { cpa_wait0(); }
        __syncthreads();
        const float* xbuf = xs + (s & 1) * K1_XBUF;
        const float* wbuf = ws + (s & 1) * K1_WBUF;
        #pragma unroll 8
        for (int kk = 0; kk < 32; kk++) {
            ull xd[8];
            #pragma unroll
            for (int i = 0; i < 8; i++) xd[i] = dup2(xbuf[(rg + 32 * i) * 36 + kk]);
            ulonglong2 w01 = *(const ulonglong2*)(wbuf + kk * 64 + c0);
            ulonglong2 w23 = *(const ulonglong2*)(wbuf + kk * 64 + c0 + 4);
            #pragma unroll
            for (int i = 0; i < 8; i++) {
                acc[i][0] = ffma2(xd[i], w01.x, acc[i][0]);
                acc[i][1] = ffma2(xd[i], w01.y, acc[i][1]);
                acc[i][2] = ffma2(xd[i], w23.x, acc[i][2]);
                acc[i][3] = ffma2(xd[i], w23.y, acc[i][3]);
            }
        }
        __syncthreads();
    }

    // epilogue: stag[64][257] (reuses xs region)
    float* stag = xs;
    float cq[8];
    #pragma unroll
    for (int j = 0; j < 8; j++) cq[j] = g_cqk[c0 + j];
    #pragma unroll
    for (int i = 0; i < 8; i++) {
        int r = rg + 32 * i;
        #pragma unroll
        for (int m = 0; m < 4; m++) {
            stag[(c0 + 2 * m) * 257 + r]     = ulo(acc[i][m]) + cq[2 * m];
            stag[(c0 + 2 * m + 1) * 257 + r] = uhi(acc[i][m]) + cq[2 * m + 1];
        }
    }
    __syncthreads();
    int b  = (int)(row0 >> 14);
    int n0 = (int)(row0 & (Nn - 1));
    #pragma unroll
    for (int t = 0; t < 16; t++) {
        int idx = tid + t * 256;
        int c = idx >> 6, rq = idx & 63;
        const float* sp = stag + c * 257 + rq * 4;
        float4 v = make_float4(sp[0], sp[1], sp[2], sp[3]);
        float* dst = (c < 32)
            ? g_qlog + ((size_t)(b * Jj + c)) * Nn + n0 + rq * 4
            : g_klog + ((size_t)(b * Jj + (c - 32))) * Nn + n0 + rq * 4;
        *(float4*)dst = v;
    }
    {   // klogT[b][n][32]
        float vv[32];
        #pragma unroll
        for (int j = 0; j < 32; j++) vv[j] = stag[(32 + j) * 257 + tid];
        float* dst = g_klogT + ((size_t)b * Nn + n0 + tid) * Jj;
        #pragma unroll
        for (int q = 0; q < 8; q++)
            *(float4*)(dst + q * 4) = make_float4(vv[q*4], vv[q*4+1], vv[q*4+2], vv[q*4+3]);
    }
}

// ---------------- K2: k-softmax stats ----------------
__global__ void k2_stats() {
    int bj = blockIdx.x;
    const float* kl = g_klog + (size_t)bj * Nn;
    __shared__ float red[256];
    int tid = threadIdx.x;
    float m = -3.4e38f;
    for (int i = tid; i < Nn / 4; i += 256) {
        float4 v = ((const float4*)kl)[i];
        m = fmaxf(m, fmaxf(fmaxf(v.x, v.y), fmaxf(v.z, v.w)));
    }
    red[tid] = m; __syncthreads();
    for (int s = 128; s > 0; s >>= 1) {
        if (tid < s) red[tid] = fmaxf(red[tid], red[tid + s]);
        __syncthreads();
    }
    float M = red[0];
    __syncthreads();
    float sum = 0.f;
    for (int i = tid; i < Nn / 4; i += 256) {
        float4 v = ((const float4*)kl)[i];
        sum += __expf(v.x - M) + __expf(v.y - M) + __expf(v.z - M) + __expf(v.w - M);
    }
    red[tid] = sum; __syncthreads();
    for (int s = 128; s > 0; s >>= 1) {
        if (tid < s) red[tid] += red[tid + s];
        __syncthreads();
    }
    if (tid == 0) { g_M[bj] = M; g_Zi[bj] = 1.0f / red[0]; }
}

// ---------------- K3: Spart = sum_n w * x, 256 n per CTA ----------------
// smem: xs[2][8][512] f32 (32768B) | wb[2][8][32] f32 (2048B)
__global__ void __launch_bounds__(256, 2) k3_S(const float* __restrict__ x) {
    extern __shared__ char sm[];
    float* xs = (float*)sm;
    float* wb = (float*)(sm + 32768);
    int tid = threadIdx.x;
    int b  = blockIdx.x >> 6;
    int ch = blockIdx.x & 63;
    int n0 = ch * 256;
    int jg = tid >> 6, dg = tid & 63;
    int j0 = jg * 8;
    int d0 = dg * 4;
    int jw = tid & 31, nnw = tid >> 5;
    float Mr = g_M[b * Jj + jw];
    float Zr = g_Zi[b * Jj + jw];
    const float* xb = x + ((size_t)b * Nn + n0) * DIMM;
    const float* kT = g_klogT + ((size_t)b * Nn + n0) * Jj;
    uint32_t xs_s = (uint32_t)__cvta_generic_to_shared(xs);

    #define K3_ISSUE(s) do {                                                     \
        int buf_ = (s) & 1;                                                      \
        const float* src_ = xb + (size_t)(s) * 8 * DIMM;                         \
        uint32_t dst_ = xs_s + (uint32_t)(buf_ * 16384);                         \
        _Pragma("unroll")                                                        \
        for (int t_ = 0; t_ < 4; t_++) {                                         \
            int c_ = tid + t_ * 256;                                             \
            cpa16(dst_ + c_ * 16, src_ + c_ * 4);                                \
        }                                                                        \
    } while (0)

    ull acc[8][4];
    #pragma unroll
    for (int i = 0; i < 8; i++)
        #pragma unroll
        for (int m = 0; m < 4; m++) acc[i][m] = 0ull;

    K3_ISSUE(0); cpa_commit();
    float wreg = kT[(size_t)nnw * Jj + jw];

    for (int s = 0; s < 32; s++) {
        if (s < 31) { K3_ISSUE(s + 1); cpa_commit(); }
        wb[(s & 1) * 256 + nnw * 32 + jw] = __expf(wreg - Mr) * Zr;
        if (s < 31) cpa_wait1(); else cpa_wait0();
        __syncthreads();
        if (s < 31) wreg = kT[((size_t)(s + 1) * 8 + nnw) * Jj + jw];
        const float* xbuf = xs + (s & 1) * 4096;
        const float* wbuf = wb + (s & 1) * 256;
        #pragma unroll
        for (int nn = 0; nn < 8; nn++) {
            ull wd[8];
            #pragma unroll
            for (int i = 0; i < 8; i++) wd[i] = dup2(wbuf[nn * 32 + j0 + i]);
            ulonglong2 x01 = *(const ulonglong2*)(xbuf + nn * 512 + d0);
            ulonglong2 x23 = *(const ulonglong2*)(xbuf + nn * 512 + 256 + d0);
            #pragma unroll
            for (int i = 0; i < 8; i++) {
                acc[i][0] = ffma2(wd[i], x01.x, acc[i][0]);
                acc[i][1] = ffma2(wd[i], x01.y, acc[i][1]);
                acc[i][2] = ffma2(wd[i], x23.x, acc[i][2]);
                acc[i][3] = ffma2(wd[i], x23.y, acc[i][3]);
            }
        }
        __syncthreads();
    }
    float* dst = g_Spart + (((size_t)b * SCH + ch) * Jj) * DIMM;
    #pragma unroll
    for (int i = 0; i < 8; i++) {
        int j = j0 + i;
        *(float4*)(dst + (size_t)j * DIMM + d0) =
            make_float4(ulo(acc[i][0]), uhi(acc[i][0]), ulo(acc[i][1]), uhi(acc[i][1]));
        *(float4*)(dst + (size_t)j * DIMM + 256 + d0) =
            make_float4(ulo(acc[i][2]), uhi(acc[i][2]), ulo(acc[i][3]), uhi(acc[i][3]));
    }
}

// ---------------- K5: reduce S partials, compute U ----------------
__global__ void k5_U(const float* __restrict__ W_in, const float* __restrict__ b_in,
                     const float* __restrict__ W_v, const float* __restrict__ W_out) {
    int bj = blockIdx.x;
    int b = bj >> 5, j = bj & 31, h = j >> 2;
    __shared__ float Srow[DIMM];
    __shared__ float T[DHh];
    __shared__ float kv[DHh];
    int tid = threadIdx.x;   // 512
    {
        float s = 0.f;
        for (int ch = 0; ch < SCH; ch++)
            s += g_Spart[(((size_t)(b * SCH + ch)) * Jj + j) * DIMM + tid];
        Srow[tid] = s;
    }
    __syncthreads();
    if (tid < DHh) {
        float t = b_in[h * DHh + tid];
        for (int D = 0; D < DIMM; D++) t += Srow[D] * W_in[(size_t)D * DIMM + h * DHh + tid];
        T[tid] = t;
    }
    __syncthreads();
    if (tid < DHh) {
        float s = 0.f;
        for (int d = 0; d < DHh; d++) s += T[d] * W_v[d * DHh + tid];
        kv[tid] = s;
    }
    __syncthreads();
    {
        float u = 0.f;
        for (int c = 0; c < DHh; c++) u += kv[c] * W_out[(size_t)(h * DHh + c) * DIMM + tid];
        g_U[(size_t)bj * DIMM + tid] = u;
    }
}

// ---------------- K6: out = b_out + softmax_q @ U ----------------
__global__ void __launch_bounds__(256) k6_out(const float* __restrict__ b_out,
                                              float* __restrict__ out) {
    __shared__ float ql[Jj * 64];
    __shared__ ull   qd[64 * Jj];
    __shared__ float us[Jj * 128];
    __shared__ float bo[128];
    int tid = threadIdx.x;
    int b = blockIdx.z;
    int n0 = blockIdx.y * 64;
    int e0 = blockIdx.x * 128;

    #pragma unroll
    for (int i = 0; i < 2; i++) {
        int idx = tid + i * 256;
        int j = idx >> 4, nq = idx & 15;
        ((float4*)ql)[j * 16 + nq] =
            *(const float4*)(g_qlog + ((size_t)(b * Jj + j)) * Nn + n0 + nq * 4);
    }
    #pragma unroll
    for (int i = 0; i < 4; i++) {
        int idx = tid + i * 256;
        int j = idx >> 5, eq = idx & 31;
        ((float4*)us)[j * 32 + eq] =
            *(const float4*)(g_U + ((size_t)(b * Jj + j)) * DIMM + e0 + eq * 4);
    }
    if (tid < 32) ((float4*)bo)[tid] = *(const float4*)(b_out + e0 + tid * 4);
    __syncthreads();
    #pragma unroll
    for (int i = 0; i < 2; i++) {
        int p = tid + i * 256;
        int n = p >> 3, h = p & 7;
        float v0 = ql[(h * 4 + 0) * 64 + n];
        float v1 = ql[(h * 4 + 1) * 64 + n];
        float v2 = ql[(h * 4 + 2) * 64 + n];
        float v3 = ql[(h * 4 + 3) * 64 + n];
        float mx = fmaxf(fmaxf(v0, v1), fmaxf(v2, v3));
        float e0f = __expf(v0 - mx), e1f = __expf(v1 - mx);
        float e2f = __expf(v2 - mx), e3f = __expf(v3 - mx);
        float inv = 1.0f / (e0f + e1f + e2f + e3f);
        qd[n * Jj + h * 4 + 0] = dup2(e0f * inv);
        qd[n * Jj + h * 4 + 1] = dup2(e1f * inv);
        qd[n * Jj + h * 4 + 2] = dup2(e2f * inv);
        qd[n * Jj + h * 4 + 3] = dup2(e3f * inv);
    }
    __syncthreads();

    int tx = tid & 15, ty = tid >> 4;
    int el = tx * 8, nl = ty * 4;
    ull acc[4][4];
    #pragma unroll
    for (int i = 0; i < 4; i++)
        #pragma unroll
        for (int p = 0; p < 4; p++) acc[i][p] = 0ull;

    #pragma unroll 4
    for (int j = 0; j < Jj; j++) {
        ull a0 = qd[(nl + 0) * Jj + j];
        ull a1 = qd[(nl + 1) * Jj + j];
        ull a2 = qd[(nl + 2) * Jj + j];
        ull a3 = qd[(nl + 3) * Jj + j];
        ulonglong2 b01 = *(const ulonglong2*)(us + j * 128 + el);
        ulonglong2 b23 = *(const ulonglong2*)(us + j * 128 + el + 4);
        acc[0][0] = ffma2(a0, b01.x, acc[0][0]); acc[0][1] = ffma2(a0, b01.y, acc[0][1]);
        acc[0][2] = ffma2(a0, b23.x, acc[0][2]); acc[0][3] = ffma2(a0, b23.y, acc[0][3]);
        acc[1][0] = ffma2(a1, b01.x, acc[1][0]); acc[1][1] = ffma2(a1, b01.y, acc[1][1]);
        acc[1][2] = ffma2(a1, b23.x, acc[1][2]); acc[1][3] = ffma2(a1, b23.y, acc[1][3]);
        acc[2][0] = ffma2(a2, b01.x, acc[2][0]); acc[2][1] = ffma2(a2, b01.y, acc[2][1]);
        acc[2][2] = ffma2(a2, b23.x, acc[2][2]); acc[2][3] = ffma2(a2, b23.y, acc[2][3]);
        acc[3][0] = ffma2(a3, b01.x, acc[3][0]); acc[3][1] = ffma2(a3, b01.y, acc[3][1]);
        acc[3][2] = ffma2(a3, b23.x, acc[3][2]); acc[3][3] = ffma2(a3, b23.y, acc[3][3]);
    }

    float* ob = out + ((size_t)b * Nn + n0 + nl) * DIMM + e0 + el;
    #pragma unroll
    for (int i = 0; i < 4; i++) {
        float4 v0, v1;
        v0.x = ulo(acc[i][0]) + bo[el + 0];
        v0.y = uhi(acc[i][0]) + bo[el + 1];
        v0.z = ulo(acc[i][1]) + bo[el + 2];
        v0.w = uhi(acc[i][1]) + bo[el + 3];
        v1.x = ulo(acc[i][2]) + bo[el + 4];
        v1.y = uhi(acc[i][2]) + bo[el + 5];
        v1.z = ulo(acc[i][3]) + bo[el + 6];
        v1.w = uhi(acc[i][3]) + bo[el + 7];
        *(float4*)(ob + (size_t)i * DIMM)     = v0;
        *(float4*)(ob + (size_t)i * DIMM + 4) = v1;
    }
}

// ---------------- launch ----------------
extern "C" void kernel_launch(void* const* d_in, const int* in_sizes, int n_in,
                              void* d_out, int out_size) {
    const float* x     = (const float*)d_in[0];
    const float* W_in  = (const float*)d_in[1];
    const float* b_in  = (const float*)d_in[2];
    const float* W_q   = (const float*)d_in[3];
    const float* W_k   = (const float*)d_in[4];
    const float* W_v   = (const float*)d_in[5];
    const float* W_out = (const float*)d_in[6];
    const float* b_out = (const float*)d_in[7];
    float* out = (float*)d_out;

    cudaFuncSetAttribute(k1_logits, cudaFuncAttributeMaxDynamicSharedMemorySize, K1_SMEM);
    cudaFuncSetAttribute(k3_S,      cudaFuncAttributeMaxDynamicSharedMemorySize, 34816);

    k0_prep<<<64, 512>>>(W_in, b_in, W_q, W_k);
    k1_logits<<<(Bb * Nn) / 256, 256, K1_SMEM>>>(x);
    k2_stats<<<Bb * Jj, 256>>>();
    k3_S<<<Bb * SCH, 256, 34816>>>(x);
    k5_U<<<Bb * Jj, 512>>>(W_in, b_in, W_v, W_out);
    dim3 g6(DIMM / 128, Nn / 64, Bb);
    k6_out<<<g6, 256>>>(b_out, out);
}

// round 4
// speedup vs baseline: 2.4131x; 1.2141x over previous
// LinearNO on GB300 — round 3: fused logits+S-partials (flash-style chunk
// rescale), precomputed q-softmax, rebuilt K6.
//  K0 : A_qk[512][64] = W_in @ blockdiag(W_q|W_k); c_qk
//  K1f: per 256-row chunk: logits = x@A_qk+c ; qsm[b][n][32] (softmax over r);
//       chunk-local k stats (m_ch,z_ch per j) ; Spart[b][ch][j][512] (x reused via L2)
//  K2b: scale[b][ch][j] = exp(m_ch - M)/Z   (tiny reduction over 64 chunks)
//  K5 : U[b][j][512] = ((S @ W_in_h + b_in_h) @ W_v) @ W_out_h,  S = sum_ch scale*Spart
//  K6 : out = b_out + qsm @ U
#include <cuda_runtime.h>
#include <cstdint>

typedef unsigned long long ull;

#define Bb   8
#define Nn   16384
#define DIMM 512
#define Hh   8
#define DHh  64
#define Rr   4
#define Jj   32
#define SCH  64          // chunks per batch (256 rows each)

// ---------------- scratch ----------------
__device__ __align__(16) float g_Aqk[DIMM * 64];
__device__ __align__(16) float g_cqk[64];
__device__ __align__(16) float g_qsm[(size_t)Bb * Nn * Jj];     // [b][n][32]
__device__ __align__(16) float g_mloc[(size_t)Bb * SCH * Jj];   // [b*64+ch][j]
__device__ __align__(16) float g_zloc[(size_t)Bb * SCH * Jj];
__device__ __align__(16) float g_scale[(size_t)Bb * SCH * Jj];
__device__ __align__(16) float g_Spart[(size_t)Bb * SCH * Jj * DIMM];
__device__ __align__(16) float g_U[(size_t)Bb * Jj * DIMM];

// ---------------- helpers ----------------
__device__ __forceinline__ ull ffma2(ull a, ull b, ull c) {
    ull d;
    asm("fma.rn.f32x2 %0, %1, %2, %3;" : "=l"(d) : "l"(a), "l"(b), "l"(c));
    return d;
}
__device__ __forceinline__ ull dup2(float f) {
    unsigned u = __float_as_uint(f);
    ull d;
    asm("mov.b64 %0, {%1, %1};" : "=l"(d) : "r"(u));
    return d;
}
__device__ __forceinline__ float ulo(ull u) { return __uint_as_float((unsigned)u); }
__device__ __forceinline__ float uhi(ull u) { return __uint_as_float((unsigned)(u >> 32)); }

__device__ __forceinline__ void cpa16(uint32_t smem_dst, const void* gsrc) {
    asm volatile("cp.async.cg.shared.global [%0], [%1], 16;" :: "r"(smem_dst), "l"(gsrc));
}
__device__ __forceinline__ void cpa_commit() { asm volatile("cp.async.commit_group;"); }
__device__ __forceinline__ void cpa_wait1() { asm volatile("cp.async.wait_group 1;"); }
__device__ __forceinline__ void cpa_wait0() { asm volatile("cp.async.wait_group 0;"); }

// ---------------- K0 ----------------
__global__ void k0_prep(const float* __restrict__ W_in, const float* __restrict__ b_in,
                        const float* __restrict__ W_q, const float* __restrict__ W_k) {
    int j = blockIdx.x;                      // 0..63 (q: 0..31, k: 32..63)
    const float* Wqk = (j < 32) ? W_q : W_k;
    int jj = j & 31, h = jj >> 2, r = jj & 3;
    int D = threadIdx.x;                     // 512 threads
    const float* wrow = W_in + (size_t)D * DIMM + h * DHh;
    float s = 0.f;
    #pragma unroll 8
    for (int d = 0; d < DHh; d++) s += wrow[d] * Wqk[d * Rr + r];
    g_Aqk[(size_t)D * 64 + j] = s;
    if (D == 0) {
        float c = 0.f;
        for (int d = 0; d < DHh; d++) c += b_in[h * DHh + d] * Wqk[d * Rr + r];
        g_cqk[j] = c;
    }
}

// ---------------- K1f: fused logits + q-softmax + chunk S-partials ----------------
// smem layout (dynamic, 100608 B):
//  phase A : xs [0,73728) = 2*256*36 f32 ; ws [73728,90112) = 2*32*64 f32
//  epilogue: wsm [0,32768) = 256*32 f32 ; stag [32768,98560) = 64*257 f32 ;
//            red [98560,100608) = 512 f32  (mred[8][32], zred[8][32])
//  phase B : wsm persists ; xs2 [32768,65536) = 2*8*512 f32
#define K1F_SMEM 100608

__global__ void __launch_bounds__(256, 2) k1f(const float* __restrict__ x) {
    extern __shared__ char sm[];
    float* xs = (float*)sm;
    float* ws = (float*)(sm + 73728);
    int tid = threadIdx.x;
    int bi  = blockIdx.x;                  // 0..511
    size_t row0 = (size_t)bi * 256;
    int b  = (int)(row0 >> 14);
    int n0 = (int)(row0 & (Nn - 1));
    const float* xb = x + row0 * DIMM;
    uint32_t xs_s = (uint32_t)__cvta_generic_to_shared(xs);
    uint32_t ws_s = (uint32_t)__cvta_generic_to_shared(ws);

    // ================= Phase A: logits =================
    int cg = tid & 7, rg = tid >> 3;
    int c0 = cg * 8;

    ull acc[8][4];
    #pragma unroll
    for (int i = 0; i < 8; i++)
        #pragma unroll
        for (int m = 0; m < 4; m++) acc[i][m] = 0ull;

    #define K1_ISSUE(s) do {                                                     \
        int buf_ = (s) & 1;                                                      \
        const float* src_ = xb + (size_t)tid * DIMM + (s) * 32;                  \
        uint32_t dst_ = xs_s + (uint32_t)(buf_ * 36864 + tid * 144);             \
        _Pragma("unroll")                                                        \
        for (int i_ = 0; i_ < 8; i_++) cpa16(dst_ + i_ * 16, src_ + i_ * 4);     \
        const float* wsrc_ = g_Aqk + (s) * 32 * 64;                              \
        uint32_t wdst_ = ws_s + (uint32_t)(buf_ * 8192);                         \
        _Pragma("unroll")                                                        \
        for (int i_ = 0; i_ < 2; i_++) {                                         \
            int c_ = tid * 2 + i_;                                               \
            cpa16(wdst_ + c_ * 16, wsrc_ + c_ * 4);                              \
        }                                                                        \
    } while (0)

    K1_ISSUE(0); cpa_commit();
    for (int s = 0; s < 16; s++) {
        if (s < 15) { K1_ISSUE(s + 1); cpa_commit(); cpa_wait1(); }
        else        { cpa_wait0(); }
        __syncthreads();
        const float* xbuf = xs + (s & 1) * 9216;
        const float* wbuf = ws + (s & 1) * 2048;
        #pragma unroll 8
        for (int kk = 0; kk < 32; kk++) {
            ull xd[8];
            #pragma unroll
            for (int i = 0; i < 8; i++) xd[i] = dup2(xbuf[(rg + 32 * i) * 36 + kk]);
            ulonglong2 w01 = *(const ulonglong2*)(wbuf + kk * 64 + c0);
            ulonglong2 w23 = *(const ulonglong2*)(wbuf + kk * 64 + c0 + 4);
            #pragma unroll
            for (int i = 0; i < 8; i++) {
                acc[i][0] = ffma2(xd[i], w01.x, acc[i][0]);
                acc[i][1] = ffma2(xd[i], w01.y, acc[i][1]);
                acc[i][2] = ffma2(xd[i], w23.x, acc[i][2]);
                acc[i][3] = ffma2(xd[i], w23.y, acc[i][3]);
            }
        }
        __syncthreads();
    }

    // ================= Epilogue: stag + q-softmax + k chunk-stats =================
    float* wsm  = (float*)sm;                  // [256 n][32 j]
    float* stag = (float*)(sm + 32768);        // [64 c][257]
    float* mred = (float*)(sm + 98560);        // [8][32]
    float* zred = mred + 256;

    {
        float cq[8];
        #pragma unroll
        for (int j = 0; j < 8; j++) cq[j] = g_cqk[c0 + j];
        #pragma unroll
        for (int i = 0; i < 8; i++) {
            int r = rg + 32 * i;
            #pragma unroll
            for (int m = 0; m < 4; m++) {
                stag[(c0 + 2 * m) * 257 + r]     = ulo(acc[i][m]) + cq[2 * m];
                stag[(c0 + 2 * m + 1) * 257 + r] = uhi(acc[i][m]) + cq[2 * m + 1];
            }
        }
    }
    __syncthreads();

    // q softmax: thread = one n
    {
        float4 qs[8];
        #pragma unroll
        for (int h = 0; h < 8; h++) {
            float v0 = stag[(4 * h + 0) * 257 + tid];
            float v1 = stag[(4 * h + 1) * 257 + tid];
            float v2 = stag[(4 * h + 2) * 257 + tid];
            float v3 = stag[(4 * h + 3) * 257 + tid];
            float mx = fmaxf(fmaxf(v0, v1), fmaxf(v2, v3));
            float e0 = __expf(v0 - mx), e1 = __expf(v1 - mx);
            float e2 = __expf(v2 - mx), e3 = __expf(v3 - mx);
            float inv = 1.0f / (e0 + e1 + e2 + e3);
            qs[h] = make_float4(e0 * inv, e1 * inv, e2 * inv, e3 * inv);
        }
        float* dst = g_qsm + ((size_t)b * Nn + n0 + tid) * Jj;
        #pragma unroll
        for (int h = 0; h < 8; h++) *(float4*)(dst + h * 4) = qs[h];
    }

    // k chunk-local stats + weights: thread = (j = tid&31, grp = tid>>5)
    {
        int j = tid & 31, grp = tid >> 5;
        const float* kl = stag + (32 + j) * 257 + grp * 32;
        float mloc = -3.4e38f;
        #pragma unroll 8
        for (int nn = 0; nn < 32; nn++) mloc = fmaxf(mloc, kl[nn]);
        mred[grp * 32 + j] = mloc;
        __syncthreads();
        float Mj = -3.4e38f;
        #pragma unroll
        for (int g = 0; g < 8; g++) Mj = fmaxf(Mj, mred[g * 32 + j]);
        float zloc = 0.f;
        #pragma unroll 8
        for (int nn = 0; nn < 32; nn++) {
            float w = __expf(kl[nn] - Mj);
            zloc += w;
            wsm[(grp * 32 + nn) * 32 + j] = w;
        }
        zred[grp * 32 + j] = zloc;
        __syncthreads();
        if (tid < 32) {
            float z = 0.f;
            #pragma unroll
            for (int g = 0; g < 8; g++) z += zred[g * 32 + tid];
            g_mloc[(size_t)bi * Jj + tid] = Mj;
            g_zloc[(size_t)bi * Jj + tid] = z;
        }
    }
    __syncthreads();   // wsm complete; stag dead -> xs2 region reusable

    // ================= Phase B: S partials =================
    float* xs2 = (float*)(sm + 32768);         // 2 * 8*512 f32
    uint32_t xs2_s = (uint32_t)__cvta_generic_to_shared(xs2);
    int jg = tid >> 6, dg = tid & 63;
    int j0 = jg * 8;
    int d0 = dg * 4;

    #define K3_ISSUE(s) do {                                                     \
        int buf_ = (s) & 1;                                                      \
        const float* src_ = xb + (size_t)(s) * 8 * DIMM;                         \
        uint32_t dst_ = xs2_s + (uint32_t)(buf_ * 16384);                        \
        _Pragma("unroll")                                                        \
        for (int t_ = 0; t_ < 4; t_++) {                                         \
            int c_ = tid + t_ * 256;                                             \
            cpa16(dst_ + c_ * 16, src_ + c_ * 4);                                \
        }                                                                        \
    } while (0)

    ull sacc[8][4];
    #pragma unroll
    for (int i = 0; i < 8; i++)
        #pragma unroll
        for (int m = 0; m < 4; m++) sacc[i][m] = 0ull;

    K3_ISSUE(0); cpa_commit();
    for (int s = 0; s < 32; s++) {
        if (s < 31) { K3_ISSUE(s + 1); cpa_commit(); cpa_wait1(); }
        else        { cpa_wait0(); }
        __syncthreads();
        const float* xbuf = xs2 + (s & 1) * 4096;
        const float* wrow = wsm + s * 8 * 32;
        #pragma unroll
        for (int nn = 0; nn < 8; nn++) {
            ull wd[8];
            #pragma unroll
            for (int i = 0; i < 8; i++) wd[i] = dup2(wrow[nn * 32 + j0 + i]);
            ulonglong2 x01 = *(const ulonglong2*)(xbuf + nn * 512 + d0);
            ulonglong2 x23 = *(const ulonglong2*)(xbuf + nn * 512 + 256 + d0);
            #pragma unroll
            for (int i = 0; i < 8; i++) {
                sacc[i][0] = ffma2(wd[i], x01.x, sacc[i][0]);
                sacc[i][1] = ffma2(wd[i], x01.y, sacc[i][1]);
                sacc[i][2] = ffma2(wd[i], x23.x, sacc[i][2]);
                sacc[i][3] = ffma2(wd[i], x23.y, sacc[i][3]);
            }
        }
        __syncthreads();
    }
    float* dst = g_Spart + ((size_t)bi * Jj) * DIMM;
    #pragma unroll
    for (int i = 0; i < 8; i++) {
        int j = j0 + i;
        *(float4*)(dst + (size_t)j * DIMM + d0) =
            make_float4(ulo(sacc[i][0]), uhi(sacc[i][0]), ulo(sacc[i][1]), uhi(sacc[i][1]));
        *(float4*)(dst + (size_t)j * DIMM + 256 + d0) =
            make_float4(ulo(sacc[i][2]), uhi(sacc[i][2]), ulo(sacc[i][3]), uhi(sacc[i][3]));
    }
}

// ---------------- K2b: combine chunk stats -> per-chunk scale ----------------
__global__ void k2b_scale() {
    int bj = blockIdx.x;              // 0..255
    int b = bj >> 5, j = bj & 31;
    __shared__ float smv[64], szv[64];
    int ch = threadIdx.x;             // 64 threads
    float m = g_mloc[(size_t)(b * SCH + ch) * Jj + j];
    float z = g_zloc[(size_t)(b * SCH + ch) * Jj + j];
    smv[ch] = m;
    __syncthreads();
    float M = -3.4e38f;
    #pragma unroll
    for (int c = 0; c < 64; c++) M = fmaxf(M, smv[c]);
    szv[ch] = z * __expf(m - M);
    __syncthreads();
    float Z = 0.f;
    #pragma unroll
    for (int c = 0; c < 64; c++) Z += szv[c];
    g_scale[(size_t)(b * SCH + ch) * Jj + j] = __expf(m - M) / Z;
}

// ---------------- K5: reduce scaled S partials, compute U ----------------
__global__ void k5_U(const float* __restrict__ W_in, const float* __restrict__ b_in,
                     const float* __restrict__ W_v, const float* __restrict__ W_out) {
    int bj = blockIdx.x;
    int b = bj >> 5, j = bj & 31, h = j >> 2;
    __shared__ float scl[SCH];
    __shared__ float Srow[DIMM];
    __shared__ float T[DHh];
    __shared__ float kv[DHh];
    int tid = threadIdx.x;   // 512
    if (tid < SCH) scl[tid] = g_scale[(size_t)(b * SCH + tid) * Jj + j];
    __syncthreads();
    {
        float s = 0.f;
        for (int ch = 0; ch < SCH; ch++)
            s += g_Spart[(((size_t)(b * SCH + ch)) * Jj + j) * DIMM + tid] * scl[ch];
        Srow[tid] = s;
    }
    __syncthreads();
    if (tid < DHh) {
        float t = b_in[h * DHh + tid];
        for (int D = 0; D < DIMM; D++) t += Srow[D] * W_in[(size_t)D * DIMM + h * DHh + tid];
        T[tid] = t;
    }
    __syncthreads();
    if (tid < DHh) {
        float s = 0.f;
        for (int d = 0; d < DHh; d++) s += T[d] * W_v[d * DHh + tid];
        kv[tid] = s;
    }
    __syncthreads();
    {
        float u = 0.f;
        for (int c = 0; c < DHh; c++) u += kv[c] * W_out[(size_t)(h * DHh + c) * DIMM + tid];
        g_U[(size_t)bj * DIMM + tid] = u;
    }
}

// ---------------- K6: out = b_out + qsm @ U  (64n x 256e per block) ----------------
__global__ void __launch_bounds__(256) k6_out(const float* __restrict__ b_out,
                                              float* __restrict__ out) {
    __shared__ float qsv[64 * 36];     // [n][36 pad]
    __shared__ float us[Jj * 256];     // [j][e]
    __shared__ float bo[256];
    int tid = threadIdx.x;
    int b = blockIdx.z;
    int n0 = blockIdx.y * 64;
    int e0 = blockIdx.x * 256;

    #pragma unroll
    for (int t = 0; t < 2; t++) {
        int idx = tid + t * 256;       // 512 float4
        int row = idx >> 3, q = idx & 7;
        float4 v = *(const float4*)(g_qsm + ((size_t)b * Nn + n0 + row) * Jj + q * 4);
        *(float4*)(qsv + row * 36 + q * 4) = v;
    }
    #pragma unroll
    for (int t = 0; t < 8; t++) {
        int idx = tid + t * 256;       // 2048 float4
        int j = idx >> 6, q = idx & 63;
        ((float4*)us)[j * 64 + q] =
            *(const float4*)(g_U + ((size_t)(b * Jj + j)) * DIMM + e0 + q * 4);
    }
    if (tid < 64) ((float4*)bo)[tid] = *(const float4*)(b_out + e0 + tid * 4);
    __syncthreads();

    int tx = tid & 15, ty = tid >> 4;
    int nl = ty * 4, eb = tx * 4;
    ull acc[4][8];
    #pragma unroll
    for (int i = 0; i < 4; i++)
        #pragma unroll
        for (int m = 0; m < 8; m++) acc[i][m] = 0ull;

    #pragma unroll 4
    for (int j = 0; j < Jj; j++) {
        ull a[4];
        #pragma unroll
        for (int i = 0; i < 4; i++) a[i] = dup2(qsv[(nl + i) * 36 + j]);
        const float* ur = us + j * 256;
        ulonglong2 u0 = *(const ulonglong2*)(ur + eb);
        ulonglong2 u1 = *(const ulonglong2*)(ur + 64 + eb);
        ulonglong2 u2 = *(const ulonglong2*)(ur + 128 + eb);
        ulonglong2 u3 = *(const ulonglong2*)(ur + 192 + eb);
        #pragma unroll
        for (int i = 0; i < 4; i++) {
            acc[i][0] = ffma2(a[i], u0.x, acc[i][0]);
            acc[i][1] = ffma2(a[i], u0.y, acc[i][1]);
            acc[i][2] = ffma2(a[i], u1.x, acc[i][2]);
            acc[i][3] = ffma2(a[i], u1.y, acc[i][3]);
            acc[i][4] = ffma2(a[i], u2.x, acc[i][4]);
            acc[i][5] = ffma2(a[i], u2.y, acc[i][5]);
            acc[i][6] = ffma2(a[i], u3.x, acc[i][6]);
            acc[i][7] = ffma2(a[i], u3.y, acc[i][7]);
        }
    }

    #pragma unroll
    for (int i = 0; i < 4; i++) {
        float* row = out + ((size_t)b * Nn + n0 + nl + i) * DIMM + e0;
        #pragma unroll
        for (int seg = 0; seg < 4; seg++) {
            float4 v;
            v.x = ulo(acc[i][2 * seg])     + bo[seg * 64 + eb + 0];
            v.y = uhi(acc[i][2 * seg])     + bo[seg * 64 + eb + 1];
            v.z = ulo(acc[i][2 * seg + 1]) + bo[seg * 64 + eb + 2];
            v.w = uhi(acc[i][2 * seg + 1]) + bo[seg * 64 + eb + 3];
            *(float4*)(row + seg * 64 + eb) = v;
        }
    }
}

// ---------------- launch ----------------
extern "C" void kernel_launch(void* const* d_in, const int* in_sizes, int n_in,
                              void* d_out, int out_size) {
    const float* x     = (const float*)d_in[0];
    const float* W_in  = (const float*)d_in[1];
    const float* b_in  = (const float*)d_in[2];
    const float* W_q   = (const float*)d_in[3];
    const float* W_k   = (const float*)d_in[4];
    const float* W_v   = (const float*)d_in[5];
    const float* W_out = (const float*)d_in[6];
    const float* b_out = (const float*)d_in[7];
    float* out = (float*)d_out;

    cudaFuncSetAttribute(k1f, cudaFuncAttributeMaxDynamicSharedMemorySize, K1F_SMEM);

    k0_prep<<<64, 512>>>(W_in, b_in, W_q, W_k);
    k1f<<<Bb * SCH, 256, K1F_SMEM>>>(x);
    k2b_scale<<<Bb * Jj, 64>>>();
    k5_U<<<Bb * Jj, 512>>>(W_in, b_in, W_v, W_out);
    dim3 g6(DIMM / 256, Nn / 64, Bb);
    k6_out<<<g6, 256>>>(b_out, out);
}